// round 2
// baseline (speedup 1.0000x reference)
#include <cuda_runtime.h>
#include <cuda_bf16.h>

// Problem constants
#define NN 8192        // sequence length N
#define RR 32          // B*G = 4*8 combined row count
#define TN 256         // n-tile per block
#define TK 16          // m (K) tile per smem stage
#define SPLITK 8
#define KCHUNK (NN / SPLITK)     // 1024
#define NSTEPS (KCHUNK / TK)     // 64
#define AS_STRIDE 260            // 256 + 4 pad (keeps 16B alignment, 2-way STS conflict only)

// Scratch (static device globals; no allocation)
__device__ float g_z[4 * RR * NN];      // z stages [k][r][n], 4 MB
__device__ float g_part[SPLITK * RR * NN];  // split-K partials, 8 MB

// ---------------------------------------------------------------------------
// Stage 0: transpose x[B,N,G] -> z0[r][n], r = b*8+g
// ---------------------------------------------------------------------------
__global__ void transpose_kernel(const float* __restrict__ x, float* __restrict__ z0) {
    int idx = blockIdx.x * 256 + threadIdx.x;   // 262144 total
    int n = idx & (NN - 1);
    int r = idx >> 13;          // 0..31
    int b = r >> 3;
    int g = r & 7;
    z0[idx] = x[((b << 13) + n) * 8 + g];
}

// ---------------------------------------------------------------------------
// GEMM: part[sp][r][n] = sum_{m in chunk sp} A[n][m] * B[r][m]
// A = S[k] (8192x8192 row-major), B = cur (32x8192 row-major)
// block: 128 threads, tile 256n x 32r; grid (32 n-blocks, 8 splits)
// ---------------------------------------------------------------------------
__global__ void __launch_bounds__(128)
gemm_kernel(const float* __restrict__ A, const float* __restrict__ B,
            float* __restrict__ part) {
    __shared__ __align__(16) float As[TK][AS_STRIDE];  // [m][n] transposed
    __shared__ __align__(16) float Bs[TK][2 * RR];     // [m][2r] value-duplicated

    const int tid = threadIdx.x;
    const int nb  = blockIdx.x;       // 0..31
    const int sp  = blockIdx.y;       // 0..7
    const int n0  = nb * TN;
    const int m0  = sp * KCHUNK;

    // A-load mapping: 4 lanes per row (64B), 32 rows per pass, 8 passes
    const int a_row = tid >> 2;            // 0..31
    const int a_mq  = (tid & 3) << 2;      // 0,4,8,12
    // B-load mapping: 128 threads cover 32r x 16m exactly (one float4 each)
    const int b_r = tid >> 2;              // 0..31
    const int b_m = (tid & 3) << 2;        // 0,4,8,12

    // compute mapping: thread tile = 4n x 16r
    const int nq = tid & 63;               // n-quad index, n_local = 4*nq
    const int r0 = (tid >> 6) << 4;        // 0 or 16

    unsigned long long acc[16][2];         // f32x2 accumulators: [r][n-pair]
#pragma unroll
    for (int i = 0; i < 16; i++) { acc[i][0] = 0ull; acc[i][1] = 0ull; }

    const float* Abase = A + (size_t)(n0 + a_row) * NN + a_mq + m0;
    const float* Bbase = B + (size_t)b_r * NN + b_m + m0;

    float4 areg[8];
    float4 breg;

    // prefetch tile 0
#pragma unroll
    for (int p = 0; p < 8; p++)
        areg[p] = *(const float4*)(Abase + (size_t)(32 * p) * NN);
    breg = *(const float4*)(Bbase);

    for (int step = 0; step < NSTEPS; step++) {
        __syncthreads();   // previous compute done -> safe to overwrite smem

        // store staged tile
#pragma unroll
        for (int p = 0; p < 8; p++) {
            int row = a_row + 32 * p;
            As[a_mq + 0][row] = areg[p].x;
            As[a_mq + 1][row] = areg[p].y;
            As[a_mq + 2][row] = areg[p].z;
            As[a_mq + 3][row] = areg[p].w;
        }
        *(float2*)&Bs[b_m + 0][2 * b_r] = make_float2(breg.x, breg.x);
        *(float2*)&Bs[b_m + 1][2 * b_r] = make_float2(breg.y, breg.y);
        *(float2*)&Bs[b_m + 2][2 * b_r] = make_float2(breg.z, breg.z);
        *(float2*)&Bs[b_m + 3][2 * b_r] = make_float2(breg.w, breg.w);
        __syncthreads();

        // prefetch next tile (global latency hidden by compute below)
        if (step + 1 < NSTEPS) {
            int mc = (step + 1) * TK;
#pragma unroll
            for (int p = 0; p < 8; p++)
                areg[p] = *(const float4*)(Abase + (size_t)(32 * p) * NN + mc);
            breg = *(const float4*)(Bbase + mc);
        }

        // compute 16 m-steps
#pragma unroll
        for (int m = 0; m < TK; m++) {
            const float4 av = *(const float4*)(&As[m][nq << 2]);
            unsigned long long a01, a23;
            asm("mov.b64 %0,{%1,%2};" : "=l"(a01) : "f"(av.x), "f"(av.y));
            asm("mov.b64 %0,{%1,%2};" : "=l"(a23) : "f"(av.z), "f"(av.w));
#pragma unroll
            for (int q = 0; q < 8; q++) {
                const float4 bv = *(const float4*)(&Bs[m][(r0 << 1) + (q << 2)]);
                unsigned long long b0, b1;
                asm("mov.b64 %0,{%1,%2};" : "=l"(b0) : "f"(bv.x), "f"(bv.y));
                asm("mov.b64 %0,{%1,%2};" : "=l"(b1) : "f"(bv.z), "f"(bv.w));
                asm("fma.rn.f32x2 %0,%1,%2,%0;" : "+l"(acc[2 * q][0])     : "l"(a01), "l"(b0));
                asm("fma.rn.f32x2 %0,%1,%2,%0;" : "+l"(acc[2 * q][1])     : "l"(a23), "l"(b0));
                asm("fma.rn.f32x2 %0,%1,%2,%0;" : "+l"(acc[2 * q + 1][0]) : "l"(a01), "l"(b1));
                asm("fma.rn.f32x2 %0,%1,%2,%0;" : "+l"(acc[2 * q + 1][1]) : "l"(a23), "l"(b1));
            }
        }
    }

    // epilogue: write partials, coalesced 16B per (r) row
#pragma unroll
    for (int i = 0; i < 16; i++) {
        float x0, x1, x2, x3;
        asm("mov.b64 {%0,%1}, %2;" : "=f"(x0), "=f"(x1) : "l"(acc[i][0]));
        asm("mov.b64 {%0,%1}, %2;" : "=f"(x2), "=f"(x3) : "l"(acc[i][1]));
        float4 v = make_float4(x0, x1, x2, x3);
        *(float4*)(part + (size_t)(sp * RR + r0 + i) * NN + n0 + (nq << 2)) = v;
    }
}

// ---------------------------------------------------------------------------
// Reduce split-K partials into next z stage
// ---------------------------------------------------------------------------
__global__ void reduce_kernel(const float* __restrict__ part, float* __restrict__ out) {
    int idx = blockIdx.x * 256 + threadIdx.x;   // over 65536 float4
    const float4* p4 = (const float4*)part;
    float4 s = p4[idx];
#pragma unroll
    for (int sI = 1; sI < SPLITK; sI++) {
        float4 t = p4[idx + sI * (RR * NN / 4)];
        s.x += t.x; s.y += t.y; s.z += t.z; s.w += t.w;
    }
    ((float4*)out)[idx] = s;
}

// ---------------------------------------------------------------------------
// Final projection with the torch-faithful raw-reshape index mapping:
// y[b,n,f] = sum_j z[n>>11][b*8+(n>>8)&7][(n&255)*32+j] * W_flat[8j+f] + bias[n>>10]
// ---------------------------------------------------------------------------
__global__ void final_kernel(const float* __restrict__ z, const float* __restrict__ W,
                             const float* __restrict__ bias, float* __restrict__ y) {
    __shared__ float Ws[256];
    __shared__ float bs[8];
    int t = threadIdx.x;
    Ws[t] = W[t];
    if (t < 8) bs[t] = bias[t];
    __syncthreads();

    int idx = blockIdx.x * 256 + t;   // b*8192 + n, 32768 total
    int n = idx & (NN - 1);
    int b = idx >> 13;
    int k0 = n >> 11;
    int g0 = (n >> 8) & 7;
    const float* zp = z + ((size_t)(k0 * RR + b * 8 + g0) << 13) + ((n & 255) << 5);

    float bb = bs[n >> 10];
    float acc[8];
#pragma unroll
    for (int f = 0; f < 8; f++) acc[f] = bb;

#pragma unroll
    for (int jq = 0; jq < 8; jq++) {
        float4 zv = *(const float4*)(zp + 4 * jq);
#pragma unroll
        for (int e = 0; e < 4; e++) {
            float zs = (e == 0) ? zv.x : (e == 1) ? zv.y : (e == 2) ? zv.z : zv.w;
            int j = 4 * jq + e;
#pragma unroll
            for (int f = 0; f < 8; f++) acc[f] += zs * Ws[8 * j + f];
        }
    }

    float4* yo = (float4*)(y + (size_t)idx * 8);
    yo[0] = make_float4(acc[0], acc[1], acc[2], acc[3]);
    yo[1] = make_float4(acc[4], acc[5], acc[6], acc[7]);
}

// ---------------------------------------------------------------------------
extern "C" void kernel_launch(void* const* d_in, const int* in_sizes, int n_in,
                              void* d_out, int out_size) {
    const float* x    = (const float*)d_in[0];   // [4,8192,8]
    const float* S    = (const float*)d_in[1];   // [3,8192,8192]
    const float* W    = (const float*)d_in[2];   // [8,1,4,8] -> flat 256
    const float* bias = (const float*)d_in[3];   // [8,1]
    float* y = (float*)d_out;                    // [4,8192,8]

    float *zbuf, *pbuf;
    cudaGetSymbolAddress((void**)&zbuf, g_z);
    cudaGetSymbolAddress((void**)&pbuf, g_part);

    transpose_kernel<<<1024, 256>>>(x, zbuf);

    for (int k = 0; k < 3; k++) {
        gemm_kernel<<<dim3(32, SPLITK), 128>>>(S + (size_t)k * NN * NN,
                                               zbuf + (size_t)k * RR * NN, pbuf);
        reduce_kernel<<<256, 256>>>(pbuf, zbuf + (size_t)(k + 1) * RR * NN);
    }

    final_kernel<<<128, 256>>>(zbuf, W, bias, y);
}

// round 3
// speedup vs baseline: 1.1544x; 1.1544x over previous
#include <cuda_runtime.h>
#include <cuda_bf16.h>

// Problem constants
#define NN 8192        // sequence length N
#define RR 32          // B*G = 4*8 combined row count
#define TN 128         // n-tile per block
#define TK 16          // m (K) tile per smem stage
#define SPLITK 8
#define KCHUNK (NN / SPLITK)     // 1024
#define NSTEPS (KCHUNK / TK)     // 64
#define A_STRIDE 20              // floats per As row: 16B-aligned, conflict-free reads

// Scratch (static device globals; no allocation)
__device__ float g_z[4 * RR * NN];          // z stages [k][r][n], 4 MB
__device__ float g_part[SPLITK * RR * NN];  // split-K partials, 8 MB

__device__ __forceinline__ unsigned smem_u32(const void* p) {
    return (unsigned)__cvta_generic_to_shared(p);
}
__device__ __forceinline__ void cp16(unsigned dst, const void* src) {
    asm volatile("cp.async.cg.shared.global [%0], [%1], 16;" :: "r"(dst), "l"(src));
}

// ---------------------------------------------------------------------------
// Stage 0: transpose x[B,N,G] -> z0[r][n], r = b*8+g
// ---------------------------------------------------------------------------
__global__ void transpose_kernel(const float* __restrict__ x, float* __restrict__ z0) {
    int idx = blockIdx.x * 256 + threadIdx.x;   // 262144 total
    int n = idx & (NN - 1);
    int r = idx >> 13;          // 0..31
    int b = r >> 3;
    int g = r & 7;
    z0[idx] = x[((b << 13) + n) * 8 + g];
}

// ---------------------------------------------------------------------------
// GEMM: part[sp][r][n] = sum_{m in chunk sp} A[n][m] * B[r][m]
// A = S[k] (8192x8192 row-major), B = cur (32x8192 row-major)
// block: 128 threads, tile 128n x 32r; grid (64 n-blocks, SPLITK)
// f32x2 packs (even m, odd m); lanes folded at epilogue.
// Both tiles arrive via cp.async in natural layout (no STS, no transpose).
// ---------------------------------------------------------------------------
__global__ void __launch_bounds__(128, 4)
gemm_kernel(const float* __restrict__ A, const float* __restrict__ B,
            float* __restrict__ part) {
    __shared__ __align__(16) float As[2][TN * A_STRIDE];  // 2 x 10240 B
    __shared__ __align__(16) float Bs[2][RR * TK];        // 2 x 2048 B

    const int tid = threadIdx.x;
    const int nb  = blockIdx.x;       // 0..63
    const int sp  = blockIdx.y;       // 0..SPLITK-1
    const int n0  = nb * TN;
    const int m0  = sp * KCHUNK;

    // cp.async mapping: A tile = 128 rows x 64B = 512 x 16B chunks, 4/thread
    const int a_row0 = tid >> 2;           // 0..31 (rows a_row0 + 32p)
    const int a_mo   = (tid & 3) << 2;     // m offset 0,4,8,12
    const float* Ab = A + (size_t)(n0 + a_row0) * NN + m0 + a_mo;
    // B tile = 32 r x 64B = 128 x 16B chunks, 1/thread
    const float* Bb = B + (size_t)(tid >> 2) * NN + m0 + a_mo;
    const unsigned a_dst_off = ((unsigned)a_row0 * A_STRIDE + a_mo) * 4u;
    const unsigned b_dst_off = (((unsigned)tid >> 2) * TK + a_mo) * 4u;

    // compute mapping: thread owns n in {nq+32j}, r in r0..r0+7
    const int nq = tid & 31;
    const int r0 = (tid >> 5) << 3;        // 0,8,16,24

    unsigned long long acc[4][8];          // f32x2: lane0 = even-m sum, lane1 = odd-m
#pragma unroll
    for (int j = 0; j < 4; j++)
#pragma unroll
        for (int i = 0; i < 8; i++) acc[j][i] = 0ull;

    // prologue: issue tile 0 into buffer 0
    {
        unsigned da = smem_u32(&As[0][0]) + a_dst_off;
        unsigned db = smem_u32(&Bs[0][0]) + b_dst_off;
#pragma unroll
        for (int p = 0; p < 4; p++)
            cp16(da + 32u * A_STRIDE * 4u * p, Ab + (size_t)(32 * p) * NN);
        cp16(db, Bb);
        asm volatile("cp.async.commit_group;");
    }

    for (int step = 0; step < NSTEPS; step++) {
        const int cur = step & 1;
        const int nxt = cur ^ 1;

        asm volatile("cp.async.wait_group 0;" ::: "memory");
        __syncthreads();   // tile `step` visible; all threads done with buffer nxt

        if (step + 1 < NSTEPS) {
            const int mc = (step + 1) * TK;
            unsigned da = smem_u32(&As[nxt][0]) + a_dst_off;
            unsigned db = smem_u32(&Bs[nxt][0]) + b_dst_off;
#pragma unroll
            for (int p = 0; p < 4; p++)
                cp16(da + 32u * A_STRIDE * 4u * p, Ab + (size_t)(32 * p) * NN + mc);
            cp16(db, Bb + mc);
            asm volatile("cp.async.commit_group;");
        }

        const float* as = &As[cur][0];
        const float* bs = &Bs[cur][0];

#pragma unroll
        for (int mq = 0; mq < TK; mq += 4) {   // 4 m per pass = 2 f32x2 pairs
            unsigned long long alo[4], ahi[4];
#pragma unroll
            for (int j = 0; j < 4; j++) {
                const float4 av = *(const float4*)(as + (nq + 32 * j) * A_STRIDE + mq);
                asm("mov.b64 %0,{%1,%2};" : "=l"(alo[j]) : "f"(av.x), "f"(av.y));
                asm("mov.b64 %0,{%1,%2};" : "=l"(ahi[j]) : "f"(av.z), "f"(av.w));
            }
#pragma unroll
            for (int i = 0; i < 8; i++) {
                const float4 bv = *(const float4*)(bs + (r0 + i) * TK + mq);
                unsigned long long blo, bhi;
                asm("mov.b64 %0,{%1,%2};" : "=l"(blo) : "f"(bv.x), "f"(bv.y));
                asm("mov.b64 %0,{%1,%2};" : "=l"(bhi) : "f"(bv.z), "f"(bv.w));
#pragma unroll
                for (int j = 0; j < 4; j++) {
                    asm("fma.rn.f32x2 %0,%1,%2,%0;" : "+l"(acc[j][i]) : "l"(alo[j]), "l"(blo));
                    asm("fma.rn.f32x2 %0,%1,%2,%0;" : "+l"(acc[j][i]) : "l"(ahi[j]), "l"(bhi));
                }
            }
        }
    }

    // epilogue: fold even/odd lanes, coalesced scalar stores (128B per (i,j) per warp)
#pragma unroll
    for (int i = 0; i < 8; i++) {
        float* prow = part + (size_t)(sp * RR + r0 + i) * NN + n0 + nq;
#pragma unroll
        for (int j = 0; j < 4; j++) {
            float lo, hi;
            asm("mov.b64 {%0,%1},%2;" : "=f"(lo), "=f"(hi) : "l"(acc[j][i]));
            prow[32 * j] = lo + hi;
        }
    }
}

// ---------------------------------------------------------------------------
// Reduce split-K partials into next z stage
// ---------------------------------------------------------------------------
__global__ void reduce_kernel(const float* __restrict__ part, float* __restrict__ out) {
    int idx = blockIdx.x * 256 + threadIdx.x;   // over 65536 float4
    const float4* p4 = (const float4*)part;
    float4 s = p4[idx];
#pragma unroll
    for (int sI = 1; sI < SPLITK; sI++) {
        float4 t = p4[idx + sI * (RR * NN / 4)];
        s.x += t.x; s.y += t.y; s.z += t.z; s.w += t.w;
    }
    ((float4*)out)[idx] = s;
}

// ---------------------------------------------------------------------------
// Final projection with the torch-faithful raw-reshape index mapping:
// y[b,n,f] = sum_j z[n>>11][b*8+(n>>8)&7][(n&255)*32+j] * W_flat[8j+f] + bias[n>>10]
// ---------------------------------------------------------------------------
__global__ void final_kernel(const float* __restrict__ z, const float* __restrict__ W,
                             const float* __restrict__ bias, float* __restrict__ y) {
    __shared__ float Ws[256];
    __shared__ float bs[8];
    int t = threadIdx.x;
    Ws[t] = W[t];
    if (t < 8) bs[t] = bias[t];
    __syncthreads();

    int idx = blockIdx.x * 256 + t;   // b*8192 + n, 32768 total
    int n = idx & (NN - 1);
    int b = idx >> 13;
    int k0 = n >> 11;
    int g0 = (n >> 8) & 7;
    const float* zp = z + ((size_t)(k0 * RR + b * 8 + g0) << 13) + ((n & 255) << 5);

    float bb = bs[n >> 10];
    float acc[8];
#pragma unroll
    for (int f = 0; f < 8; f++) acc[f] = bb;

#pragma unroll
    for (int jq = 0; jq < 8; jq++) {
        float4 zv = *(const float4*)(zp + 4 * jq);
#pragma unroll
        for (int e = 0; e < 4; e++) {
            float zs = (e == 0) ? zv.x : (e == 1) ? zv.y : (e == 2) ? zv.z : zv.w;
            int j = 4 * jq + e;
#pragma unroll
            for (int f = 0; f < 8; f++) acc[f] += zs * Ws[8 * j + f];
        }
    }

    float4* yo = (float4*)(y + (size_t)idx * 8);
    yo[0] = make_float4(acc[0], acc[1], acc[2], acc[3]);
    yo[1] = make_float4(acc[4], acc[5], acc[6], acc[7]);
}

// ---------------------------------------------------------------------------
extern "C" void kernel_launch(void* const* d_in, const int* in_sizes, int n_in,
                              void* d_out, int out_size) {
    const float* x    = (const float*)d_in[0];   // [4,8192,8]
    const float* S    = (const float*)d_in[1];   // [3,8192,8192]
    const float* W    = (const float*)d_in[2];   // [8,1,4,8] -> flat 256
    const float* bias = (const float*)d_in[3];   // [8,1]
    float* y = (float*)d_out;                    // [4,8192,8]

    float *zbuf, *pbuf;
    cudaGetSymbolAddress((void**)&zbuf, g_z);
    cudaGetSymbolAddress((void**)&pbuf, g_part);

    transpose_kernel<<<1024, 256>>>(x, zbuf);

    for (int k = 0; k < 3; k++) {
        gemm_kernel<<<dim3(64, SPLITK), 128>>>(S + (size_t)k * NN * NN,
                                               zbuf + (size_t)k * RR * NN, pbuf);
        reduce_kernel<<<256, 256>>>(pbuf, zbuf + (size_t)(k + 1) * RR * NN);
    }

    final_kernel<<<128, 256>>>(zbuf, W, bias, y);
}